// round 4
// baseline (speedup 1.0000x reference)
#include <cuda_runtime.h>
#include <math.h>
#include <stdint.h>

#define T_TOK 8192
#define DIM   768
#define FF    3072
#define NE    8
#define CAP   2560
#define MAXR  5120   // 2*CAP, max gathered rows per expert

// ---------------- static device scratch ----------------
__device__ float g_H[(size_t)NE * MAXR * FF];
__device__ float g_Y[(size_t)NE * MAXR * DIM];
__device__ int   g_tok[NE * MAXR];
__device__ int   g_topk[T_TOK * 2];
__device__ float g_topp[T_TOK * 2];
__device__ int   g_rowidx[T_TOK * 2];
__device__ float g_wk[T_TOK * 2];
__device__ int   g_cnt[NE];
__device__ int   g_cnta[NE];
__device__ float g_psum[NE];
__device__ float g_zsum;

// ---------------- helpers ----------------
__device__ __forceinline__ uint32_t f2tf(float f) {
    uint32_t r;
    asm("cvt.rna.tf32.f32 %0, %1;" : "=r"(r) : "f"(f));
    return r;
}

#define MMA_TF32(D, A, B0, B1)                                                   \
    asm volatile(                                                                \
        "mma.sync.aligned.m16n8k8.row.col.f32.tf32.tf32.f32 "                    \
        "{%0,%1,%2,%3}, {%4,%5,%6,%7}, {%8,%9}, {%0,%1,%2,%3};\n"                \
        : "+f"((D)[0]), "+f"((D)[1]), "+f"((D)[2]), "+f"((D)[3])                 \
        : "r"((A)[0]), "r"((A)[1]), "r"((A)[2]), "r"((A)[3]), "r"(B0), "r"(B1))

// ---------------- init ----------------
__global__ void init_kernel() {
    int tid = threadIdx.x;
    if (tid < NE) { g_psum[tid] = 0.f; g_cnta[tid] = 0; }
    if (tid == 0) g_zsum = 0.f;
}

// ---------------- router ----------------
__global__ void router_kernel(const float* __restrict__ x, const float* __restrict__ wg) {
    __shared__ float sg[NE * DIM];
    __shared__ float shp[NE];
    __shared__ int   shc[NE];
    __shared__ float shz;
    int tid = threadIdx.x;
    for (int i = tid; i < NE * DIM; i += 256) sg[i] = wg[i];
    if (tid < NE) { shp[tid] = 0.f; shc[tid] = 0; }
    if (tid == 0) shz = 0.f;
    __syncthreads();

    int w = tid >> 5, lane = tid & 31;
    int t = blockIdx.x * 8 + w;
    const float* xt = x + (size_t)t * DIM;
    float acc[NE];
#pragma unroll
    for (int e = 0; e < NE; e++) acc[e] = 0.f;
    for (int j = lane; j < DIM; j += 32) {
        float xv = xt[j];
#pragma unroll
        for (int e = 0; e < NE; e++) acc[e] += xv * sg[e * DIM + j];
    }
#pragma unroll
    for (int o = 16; o > 0; o >>= 1) {
#pragma unroll
        for (int e = 0; e < NE; e++) acc[e] += __shfl_xor_sync(0xffffffffu, acc[e], o);
    }
    if (lane == 0) {
        float m = acc[0];
#pragma unroll
        for (int e = 1; e < NE; e++) m = fmaxf(m, acc[e]);
        float p[NE]; float s = 0.f;
#pragma unroll
        for (int e = 0; e < NE; e++) { p[e] = expf(acc[e] - m); s += p[e]; }
        float inv = 1.f / s;
#pragma unroll
        for (int e = 0; e < NE; e++) p[e] *= inv;
        float lse = m + logf(s);
        int i0 = 0; float b0 = p[0];
#pragma unroll
        for (int e = 1; e < NE; e++) if (p[e] > b0) { b0 = p[e]; i0 = e; }
        int i1 = -1; float b1 = -1.f;
#pragma unroll
        for (int e = 0; e < NE; e++) if (e != i0 && p[e] > b1) { b1 = p[e]; i1 = e; }
        float invs = 1.f / (b0 + b1);
        g_topk[t * 2] = i0; g_topk[t * 2 + 1] = i1;
        g_topp[t * 2] = b0 * invs; g_topp[t * 2 + 1] = b1 * invs;
#pragma unroll
        for (int e = 0; e < NE; e++) atomicAdd(&shp[e], p[e]);
        atomicAdd(&shc[i0], 1);
        atomicAdd(&shc[i1], 1);
        atomicAdd(&shz, lse * lse);
    }
    __syncthreads();
    if (tid < NE) { atomicAdd(&g_psum[tid], shp[tid]); atomicAdd(&g_cnta[tid], shc[tid]); }
    if (tid == 0) atomicAdd(&g_zsum, shz);
}

// ---------------- scan: ballot-based deterministic rank/capacity ----------------
__global__ void scan_kernel() {
    int e = blockIdx.x;
    int tid = threadIdx.x;
    int w = tid >> 5, lane = tid & 31;
    unsigned ltm = (1u << lane) - 1u;
    __shared__ int sw0[8], sw1[8], sws[8];
    __shared__ int base0, base1, baseS;
    if (tid == 0) { base0 = 0; base1 = 0; baseS = 0; }
    __syncthreads();
    for (int b = 0; b < T_TOK; b += 256) {
        int t = b + tid;
        int i0 = g_topk[t * 2], i1 = g_topk[t * 2 + 1];
        int a0 = (i0 == e) ? 1 : 0;
        int a1 = (i1 == e) ? 1 : 0;
        unsigned m0b = __ballot_sync(0xffffffffu, a0);
        unsigned m1b = __ballot_sync(0xffffffffu, a1);
        if (lane == 0) { sw0[w] = __popc(m0b); sw1[w] = __popc(m1b); }
        __syncthreads();
        int off0 = base0, off1 = base1;
        for (int j = 0; j < w; j++) { off0 += sw0[j]; off1 += sw1[j]; }
        int r0 = off0 + __popc(m0b & ltm);
        int r1 = off1 + __popc(m1b & ltm);
        int k0 = a0 && (r0 < CAP);
        int k1 = a1 && (r1 < CAP);
        int sel = (k0 || k1) ? 1 : 0;
        unsigned msb = __ballot_sync(0xffffffffu, sel);
        if (lane == 0) sws[w] = __popc(msb);
        __syncthreads();
        int offS = baseS;
        for (int j = 0; j < w; j++) offS += sws[j];
        int pos = offS + __popc(msb & ltm);
        if (sel) g_tok[e * MAXR + pos] = t;
        if (a0) { g_wk[t * 2]     = k0 ? g_topp[t * 2]     : 0.f; g_rowidx[t * 2]     = k0 ? (e * MAXR + pos) : 0; }
        if (a1) { g_wk[t * 2 + 1] = k1 ? g_topp[t * 2 + 1] : 0.f; g_rowidx[t * 2 + 1] = k1 ? (e * MAXR + pos) : 0; }
        __syncthreads();
        if (tid == 0) {
            int t0 = 0, t1 = 0, ts = 0;
            for (int j = 0; j < 8; j++) { t0 += sw0[j]; t1 += sw1[j]; ts += sws[j]; }
            base0 += t0; base1 += t1; baseS += ts;
        }
        __syncthreads();
    }
    if (tid == 0) g_cnt[e] = baseS;
}

// ---------------- GEMM config ----------------
#define BM 128
#define BN 128
#define BK 16
#define LDT 20           // padded smem row stride (u32 units), conflict-free
#define MATSZ (BM * LDT) // 2560 u32 per matrix buffer

#define CVT4(dst, v)                                                                 \
    do { uint4 cvt_; cvt_.x = f2tf((v).x); cvt_.y = f2tf((v).y);                     \
         cvt_.z = f2tf((v).z); cvt_.w = f2tf((v).w); *(uint4*)(dst) = cvt_; } while (0)

// GEMM1: H = silu(Xg @ Wg^T) * (Xg @ Wu^T); BM=128, BN=128, warps 2(m)x4(n), warp tile 64x32
__global__ __launch_bounds__(256) void gemm1_kernel(const float* __restrict__ x,
                                                    const float* __restrict__ wig,
                                                    const float* __restrict__ wiu) {
    int e = blockIdx.z;
    int cnt = g_cnt[e];
    int m0 = blockIdx.y * BM;
    if (m0 >= cnt) return;
    int n0 = blockIdx.x * BN;

    extern __shared__ uint32_t smem[];
    uint32_t* As = smem;              // [2][MATSZ]
    uint32_t* Bg = smem + 2 * MATSZ;  // [2][MATSZ]
    uint32_t* Bu = smem + 4 * MATSZ;  // [2][MATSZ]
    __shared__ int stok[BM];

    int tid = threadIdx.x;
    if (tid < BM) {
        int r = m0 + tid;
        stok[tid] = (r < cnt) ? g_tok[e * MAXR + r] : 0;
    }
    __syncthreads();

    int q  = tid & 3;   // 4-float quad within BK=16
    int rA = tid >> 2;  // 0..63 -> rows rA and rA+64
    const float* xr0 = x + (size_t)stok[rA] * DIM + q * 4;
    const float* xr1 = x + (size_t)stok[rA + 64] * DIM + q * 4;
    const float* gp0 = wig + ((size_t)e * FF + n0 + rA) * DIM + q * 4;
    const float* gp1 = gp0 + (size_t)64 * DIM;
    const float* up0 = wiu + ((size_t)e * FF + n0 + rA) * DIM + q * 4;
    const float* up1 = up0 + (size_t)64 * DIM;

    int lane = tid & 31, wid = tid >> 5;
    int g = lane >> 2, t4 = lane & 3;
    int wm = wid & 1, wn = wid >> 1;   // 2 x 4 warp grid

    float ag[4][4][4], au[4][4][4];
#pragma unroll
    for (int i = 0; i < 4; i++)
#pragma unroll
        for (int j = 0; j < 4; j++)
#pragma unroll
            for (int c = 0; c < 4; c++) { ag[i][j][c] = 0.f; au[i][j][c] = 0.f; }

    float4 vA0, vA1, vG0, vG1, vU0, vU1;

#define G1_LDG(kk)                                        \
    do {                                                  \
        vA0 = *(const float4*)(xr0 + (kk));               \
        vA1 = *(const float4*)(xr1 + (kk));               \
        vG0 = *(const float4*)(gp0 + (kk));               \
        vG1 = *(const float4*)(gp1 + (kk));               \
        vU0 = *(const float4*)(up0 + (kk));               \
        vU1 = *(const float4*)(up1 + (kk));               \
    } while (0)

#define G1_STS(buf)                                                              \
    do {                                                                         \
        uint32_t* pA_ = As + (buf) * MATSZ;                                      \
        uint32_t* pG_ = Bg + (buf) * MATSZ;                                      \
        uint32_t* pU_ = Bu + (buf) * MATSZ;                                      \
        CVT4(&pA_[rA * LDT + q * 4], vA0);                                       \
        CVT4(&pA_[(rA + 64) * LDT + q * 4], vA1);                                \
        CVT4(&pG_[rA * LDT + q * 4], vG0);                                       \
        CVT4(&pG_[(rA + 64) * LDT + q * 4], vG1);                                \
        CVT4(&pU_[rA * LDT + q * 4], vU0);                                       \
        CVT4(&pU_[(rA + 64) * LDT + q * 4], vU1);                                \
    } while (0)

    const int NK = DIM / BK;  // 48
    G1_LDG(0);
    G1_STS(0);
    __syncthreads();
    for (int kt = 0; kt < NK; kt++) {
        int cur = kt & 1;
        if (kt + 1 < NK) G1_LDG((kt + 1) * BK);
        const uint32_t* A  = As + cur * MATSZ;
        const uint32_t* BG = Bg + cur * MATSZ;
        const uint32_t* BU = Bu + cur * MATSZ;
#pragma unroll
        for (int km = 0; km < 2; km++) {
            int kb = km * 8;
            uint32_t a[4][4];
#pragma unroll
            for (int im = 0; im < 4; im++) {
                int r = wm * 64 + im * 16 + g;
                a[im][0] = A[r * LDT + kb + t4];
                a[im][1] = A[(r + 8) * LDT + kb + t4];
                a[im][2] = A[r * LDT + kb + t4 + 4];
                a[im][3] = A[(r + 8) * LDT + kb + t4 + 4];
            }
#pragma unroll
            for (int jn = 0; jn < 4; jn++) {
                int n = wn * 32 + jn * 8 + g;
                uint32_t g0 = BG[n * LDT + kb + t4], g1 = BG[n * LDT + kb + t4 + 4];
                uint32_t u0 = BU[n * LDT + kb + t4], u1 = BU[n * LDT + kb + t4 + 4];
#pragma unroll
                for (int im = 0; im < 4; im++) {
                    MMA_TF32(ag[im][jn], a[im], g0, g1);
                    MMA_TF32(au[im][jn], a[im], u0, u1);
                }
            }
        }
        if (kt + 1 < NK) { G1_STS(cur ^ 1); __syncthreads(); }
    }

    // epilogue: h = silu(g) * u
#pragma unroll
    for (int im = 0; im < 4; im++) {
#pragma unroll
        for (int jn = 0; jn < 4; jn++) {
            int rl  = wm * 64 + im * 16 + g;
            int col = n0 + wn * 32 + jn * 8 + t4 * 2;
            size_t b0i = (size_t)(e * MAXR + m0 + rl) * FF + col;
            size_t b1i = (size_t)(e * MAXR + m0 + rl + 8) * FF + col;
            float2 h0, h1;
            float gg, uu;
            gg = ag[im][jn][0]; uu = au[im][jn][0]; h0.x = gg / (1.f + expf(-gg)) * uu;
            gg = ag[im][jn][1]; uu = au[im][jn][1]; h0.y = gg / (1.f + expf(-gg)) * uu;
            gg = ag[im][jn][2]; uu = au[im][jn][2]; h1.x = gg / (1.f + expf(-gg)) * uu;
            gg = ag[im][jn][3]; uu = au[im][jn][3]; h1.y = gg / (1.f + expf(-gg)) * uu;
            *(float2*)&g_H[b0i] = h0;
            *(float2*)&g_H[b1i] = h1;
        }
    }
}

// GEMM2: Y = H @ Wo^T; BM=128, BN=128, warps 2x4, warp tile 64x32
__global__ __launch_bounds__(256) void gemm2_kernel(const float* __restrict__ wo) {
    int e = blockIdx.z;
    int cnt = g_cnt[e];
    int m0 = blockIdx.y * BM;
    if (m0 >= cnt) return;
    int n0 = blockIdx.x * BN;

    __shared__ __align__(16) uint32_t As[2][MATSZ];
    __shared__ __align__(16) uint32_t Bs[2][MATSZ];

    int tid = threadIdx.x;
    int q  = tid & 3;
    int rA = tid >> 2;
    const float* ap0 = g_H + (size_t)(e * MAXR + m0 + rA) * FF + q * 4;
    const float* ap1 = ap0 + (size_t)64 * FF;
    const float* bp0 = wo + ((size_t)e * DIM + n0 + rA) * FF + q * 4;
    const float* bp1 = bp0 + (size_t)64 * FF;

    int lane = tid & 31, wid = tid >> 5;
    int g = lane >> 2, t4 = lane & 3;
    int wm = wid & 1, wn = wid >> 1;

    float acc[4][4][4];
#pragma unroll
    for (int i = 0; i < 4; i++)
#pragma unroll
        for (int j = 0; j < 4; j++)
#pragma unroll
            for (int c = 0; c < 4; c++) acc[i][j][c] = 0.f;

    float4 vA0, vA1, vB0, vB1;

#define G2_LDG(kk)                                        \
    do {                                                  \
        vA0 = *(const float4*)(ap0 + (kk));               \
        vA1 = *(const float4*)(ap1 + (kk));               \
        vB0 = *(const float4*)(bp0 + (kk));               \
        vB1 = *(const float4*)(bp1 + (kk));               \
    } while (0)

#define G2_STS(buf)                                       \
    do {                                                  \
        CVT4(&As[buf][rA * LDT + q * 4], vA0);            \
        CVT4(&As[buf][(rA + 64) * LDT + q * 4], vA1);     \
        CVT4(&Bs[buf][rA * LDT + q * 4], vB0);            \
        CVT4(&Bs[buf][(rA + 64) * LDT + q * 4], vB1);     \
    } while (0)

    const int NK = FF / BK;  // 192
    G2_LDG(0);
    G2_STS(0);
    __syncthreads();
    for (int kt = 0; kt < NK; kt++) {
        int cur = kt & 1;
        if (kt + 1 < NK) G2_LDG((kt + 1) * BK);
        const uint32_t* A = As[cur];
        const uint32_t* B = Bs[cur];
#pragma unroll
        for (int km = 0; km < 2; km++) {
            int kb = km * 8;
            uint32_t a[4][4];
#pragma unroll
            for (int im = 0; im < 4; im++) {
                int r = wm * 64 + im * 16 + g;
                a[im][0] = A[r * LDT + kb + t4];
                a[im][1] = A[(r + 8) * LDT + kb + t4];
                a[im][2] = A[r * LDT + kb + t4 + 4];
                a[im][3] = A[(r + 8) * LDT + kb + t4 + 4];
            }
#pragma unroll
            for (int jn = 0; jn < 4; jn++) {
                int n = wn * 32 + jn * 8 + g;
                uint32_t b0 = B[n * LDT + kb + t4], b1 = B[n * LDT + kb + t4 + 4];
#pragma unroll
                for (int im = 0; im < 4; im++) MMA_TF32(acc[im][jn], a[im], b0, b1);
            }
        }
        if (kt + 1 < NK) { G2_STS(cur ^ 1); __syncthreads(); }
    }

#pragma unroll
    for (int im = 0; im < 4; im++) {
#pragma unroll
        for (int jn = 0; jn < 4; jn++) {
            int rl  = wm * 64 + im * 16 + g;
            int col = n0 + wn * 32 + jn * 8 + t4 * 2;
            size_t b0i = (size_t)(e * MAXR + m0 + rl) * DIM + col;
            size_t b1i = (size_t)(e * MAXR + m0 + rl + 8) * DIM + col;
            *(float2*)&g_Y[b0i] = make_float2(acc[im][jn][0], acc[im][jn][1]);
            *(float2*)&g_Y[b1i] = make_float2(acc[im][jn][2], acc[im][jn][3]);
        }
    }
}

// ---------------- combine ----------------
__global__ void combine_kernel(float* __restrict__ out) {
    int gi = blockIdx.x * 256 + threadIdx.x;
    int t = gi / (DIM / 4);
    int c = (gi % (DIM / 4)) * 4;
    float w0 = g_wk[t * 2], w1 = g_wk[t * 2 + 1];
    float4 acc = make_float4(0.f, 0.f, 0.f, 0.f);
    if (w0 > 0.f) {
        const float4 y = *(const float4*)&g_Y[(size_t)g_rowidx[t * 2] * DIM + c];
        acc.x = w0 * y.x; acc.y = w0 * y.y; acc.z = w0 * y.z; acc.w = w0 * y.w;
    }
    if (w1 > 0.f) {
        const float4 y = *(const float4*)&g_Y[(size_t)g_rowidx[t * 2 + 1] * DIM + c];
        acc.x += w1 * y.x; acc.y += w1 * y.y; acc.z += w1 * y.z; acc.w += w1 * y.w;
    }
    *(float4*)(out + (size_t)gi * 4) = acc;
}

// ---------------- finalize ----------------
__global__ void finalize_kernel(float* __restrict__ out, int out_size) {
    if (threadIdx.x == 0 && out_size > T_TOK * DIM) {
        float lb = 0.f;
        for (int e = 0; e < NE; e++) {
            float f = (float)g_cnta[e] / (float)(T_TOK * 2);
            float P = g_psum[e] / (float)T_TOK;
            lb += f * P;
        }
        lb *= (float)NE;
        float z = g_zsum / (float)T_TOK;
        out[T_TOK * DIM] = 0.01f * lb + 0.001f * z;
    }
}

// ---------------- launch ----------------
extern "C" void kernel_launch(void* const* d_in, const int* in_sizes, int n_in,
                              void* d_out, int out_size) {
    (void)in_sizes; (void)n_in;
    const float* x   = (const float*)d_in[0];
    const float* wg  = (const float*)d_in[1];
    const float* wig = (const float*)d_in[2];
    const float* wiu = (const float*)d_in[3];
    const float* wo  = (const float*)d_in[4];
    float* out = (float*)d_out;

    const int G1_SMEM = 6 * MATSZ * 4;  // 61440 bytes (3 matrices x 2 buffers)
    cudaFuncSetAttribute(gemm1_kernel, cudaFuncAttributeMaxDynamicSharedMemorySize, G1_SMEM);

    init_kernel<<<1, 32>>>();
    router_kernel<<<T_TOK / 8, 256>>>(x, wg);
    scan_kernel<<<NE, 256>>>();
    gemm1_kernel<<<dim3(FF / BN, MAXR / BM, NE), 256, G1_SMEM>>>(x, wig, wiu);
    gemm2_kernel<<<dim3(DIM / BN, MAXR / BM, NE), 256>>>(wo);
    combine_kernel<<<(T_TOK * DIM / 4) / 256, 256>>>(out);
    finalize_kernel<<<1, 1>>>(out, out_size);
}

// round 5
// speedup vs baseline: 1.8211x; 1.8211x over previous
#include <cuda_runtime.h>
#include <cuda_fp16.h>
#include <math.h>
#include <stdint.h>

#define T_TOK 8192
#define DIM   768
#define FF    3072
#define NE    8
#define CAP   2560
#define MAXR  5120   // 2*CAP, max gathered rows per expert

// ---------------- static device scratch ----------------
__device__ __half g_Wg_h[(size_t)NE * FF * DIM];
__device__ __half g_Wu_h[(size_t)NE * FF * DIM];
__device__ __half g_Wo_h[(size_t)NE * DIM * FF];
__device__ __half g_X_h[(size_t)T_TOK * DIM];
__device__ __half g_H_h[(size_t)NE * MAXR * FF];
__device__ float  g_Y[(size_t)NE * MAXR * DIM];
__device__ int    g_tok[NE * MAXR];
__device__ int    g_topk[T_TOK * 2];
__device__ float  g_topp[T_TOK * 2];
__device__ int    g_rowidx[T_TOK * 2];
__device__ float  g_wk[T_TOK * 2];
__device__ int    g_cnt[NE];
__device__ int    g_cnta[NE];
__device__ float  g_psum[NE];
__device__ float  g_zsum;

// ---------------- helpers ----------------
__device__ __forceinline__ uint32_t su32(const void* p) {
    uint32_t a;
    asm("{ .reg .u64 t; cvta.to.shared.u64 t, %1; cvt.u32.u64 %0, t; }" : "=r"(a) : "l"(p));
    return a;
}
__device__ __forceinline__ void cp16(uint32_t dst, const void* src) {
    asm volatile("cp.async.cg.shared.global [%0], [%1], 16;" :: "r"(dst), "l"(src) : "memory");
}
#define CP_COMMIT() asm volatile("cp.async.commit_group;" ::: "memory")
#define CP_WAIT_1() asm volatile("cp.async.wait_group 1;" ::: "memory")

#define MMA_F16(D, A, B0, B1)                                                    \
    asm volatile(                                                                \
        "mma.sync.aligned.m16n8k16.row.col.f32.f16.f16.f32 "                     \
        "{%0,%1,%2,%3}, {%4,%5,%6,%7}, {%8,%9}, {%0,%1,%2,%3};\n"                \
        : "+f"((D)[0]), "+f"((D)[1]), "+f"((D)[2]), "+f"((D)[3])                 \
        : "r"((A)[0]), "r"((A)[1]), "r"((A)[2]), "r"((A)[3]), "r"(B0), "r"(B1))

// ---------------- init ----------------
__global__ void init_kernel() {
    int tid = threadIdx.x;
    if (tid < NE) { g_psum[tid] = 0.f; g_cnta[tid] = 0; }
    if (tid == 0) g_zsum = 0.f;
}

// ---------------- fp32 -> fp16 conversion pass ----------------
// which: 0 = g_X_h, 1 = g_Wg_h, 2 = g_Wu_h, 3 = g_Wo_h
__global__ void cvt_half_kernel(const float* __restrict__ s, int which, int n8) {
    int i = blockIdx.x * blockDim.x + threadIdx.x;
    if (i >= n8) return;
    __half* d = (which == 0) ? g_X_h : (which == 1) ? g_Wg_h : (which == 2) ? g_Wu_h : g_Wo_h;
    float4 v0 = ((const float4*)s)[2 * i];
    float4 v1 = ((const float4*)s)[2 * i + 1];
    __half2 h0 = __floats2half2_rn(v0.x, v0.y);
    __half2 h1 = __floats2half2_rn(v0.z, v0.w);
    __half2 h2 = __floats2half2_rn(v1.x, v1.y);
    __half2 h3 = __floats2half2_rn(v1.z, v1.w);
    uint4 o;
    o.x = *(const uint32_t*)&h0; o.y = *(const uint32_t*)&h1;
    o.z = *(const uint32_t*)&h2; o.w = *(const uint32_t*)&h3;
    ((uint4*)d)[i] = o;
}

// ---------------- router ----------------
__global__ void router_kernel(const float* __restrict__ x, const float* __restrict__ wg) {
    __shared__ float sg[NE * DIM];
    __shared__ float shp[NE];
    __shared__ int   shc[NE];
    __shared__ float shz;
    int tid = threadIdx.x;
    for (int i = tid; i < NE * DIM; i += 256) sg[i] = wg[i];
    if (tid < NE) { shp[tid] = 0.f; shc[tid] = 0; }
    if (tid == 0) shz = 0.f;
    __syncthreads();

    int w = tid >> 5, lane = tid & 31;
    int t = blockIdx.x * 8 + w;
    const float* xt = x + (size_t)t * DIM;
    float acc[NE];
#pragma unroll
    for (int e = 0; e < NE; e++) acc[e] = 0.f;
    for (int j = lane; j < DIM; j += 32) {
        float xv = xt[j];
#pragma unroll
        for (int e = 0; e < NE; e++) acc[e] += xv * sg[e * DIM + j];
    }
#pragma unroll
    for (int o = 16; o > 0; o >>= 1) {
#pragma unroll
        for (int e = 0; e < NE; e++) acc[e] += __shfl_xor_sync(0xffffffffu, acc[e], o);
    }
    if (lane == 0) {
        float m = acc[0];
#pragma unroll
        for (int e = 1; e < NE; e++) m = fmaxf(m, acc[e]);
        float p[NE]; float s = 0.f;
#pragma unroll
        for (int e = 0; e < NE; e++) { p[e] = expf(acc[e] - m); s += p[e]; }
        float inv = 1.f / s;
#pragma unroll
        for (int e = 0; e < NE; e++) p[e] *= inv;
        float lse = m + logf(s);
        int i0 = 0; float b0 = p[0];
#pragma unroll
        for (int e = 1; e < NE; e++) if (p[e] > b0) { b0 = p[e]; i0 = e; }
        int i1 = -1; float b1 = -1.f;
#pragma unroll
        for (int e = 0; e < NE; e++) if (e != i0 && p[e] > b1) { b1 = p[e]; i1 = e; }
        float invs = 1.f / (b0 + b1);
        g_topk[t * 2] = i0; g_topk[t * 2 + 1] = i1;
        g_topp[t * 2] = b0 * invs; g_topp[t * 2 + 1] = b1 * invs;
#pragma unroll
        for (int e = 0; e < NE; e++) atomicAdd(&shp[e], p[e]);
        atomicAdd(&shc[i0], 1);
        atomicAdd(&shc[i1], 1);
        atomicAdd(&shz, lse * lse);
    }
    __syncthreads();
    if (tid < NE) { atomicAdd(&g_psum[tid], shp[tid]); atomicAdd(&g_cnta[tid], shc[tid]); }
    if (tid == 0) atomicAdd(&g_zsum, shz);
}

// ---------------- scan: ballot-based deterministic rank/capacity ----------------
__global__ void scan_kernel() {
    int e = blockIdx.x;
    int tid = threadIdx.x;
    int w = tid >> 5, lane = tid & 31;
    unsigned ltm = (1u << lane) - 1u;
    __shared__ int sw0[8], sw1[8], sws[8];
    __shared__ int base0, base1, baseS;
    if (tid == 0) { base0 = 0; base1 = 0; baseS = 0; }
    __syncthreads();
    for (int b = 0; b < T_TOK; b += 256) {
        int t = b + tid;
        int i0 = g_topk[t * 2], i1 = g_topk[t * 2 + 1];
        int a0 = (i0 == e) ? 1 : 0;
        int a1 = (i1 == e) ? 1 : 0;
        unsigned m0b = __ballot_sync(0xffffffffu, a0);
        unsigned m1b = __ballot_sync(0xffffffffu, a1);
        if (lane == 0) { sw0[w] = __popc(m0b); sw1[w] = __popc(m1b); }
        __syncthreads();
        int off0 = base0, off1 = base1;
        for (int j = 0; j < w; j++) { off0 += sw0[j]; off1 += sw1[j]; }
        int r0 = off0 + __popc(m0b & ltm);
        int r1 = off1 + __popc(m1b & ltm);
        int k0 = a0 && (r0 < CAP);
        int k1 = a1 && (r1 < CAP);
        int sel = (k0 || k1) ? 1 : 0;
        unsigned msb = __ballot_sync(0xffffffffu, sel);
        if (lane == 0) sws[w] = __popc(msb);
        __syncthreads();
        int offS = baseS;
        for (int j = 0; j < w; j++) offS += sws[j];
        int pos = offS + __popc(msb & ltm);
        if (sel) g_tok[e * MAXR + pos] = t;
        if (a0) { g_wk[t * 2]     = k0 ? g_topp[t * 2]     : 0.f; g_rowidx[t * 2]     = k0 ? (e * MAXR + pos) : 0; }
        if (a1) { g_wk[t * 2 + 1] = k1 ? g_topp[t * 2 + 1] : 0.f; g_rowidx[t * 2 + 1] = k1 ? (e * MAXR + pos) : 0; }
        __syncthreads();
        if (tid == 0) {
            int t0 = 0, t1 = 0, ts = 0;
            for (int j = 0; j < 8; j++) { t0 += sw0[j]; t1 += sw1[j]; ts += sws[j]; }
            base0 += t0; base1 += t1; baseS += ts;
        }
        __syncthreads();
    }
    if (tid == 0) g_cnt[e] = baseS;
}

// ---------------- GEMM config ----------------
#define BM 128
#define BN 128
#define BK 32                    // halves per k-tile (2 x k16 mma steps)
#define LDH 40                   // halves per smem row (32 data + 8 pad), conflict-free
#define TILE_HALF (BM * LDH)     // 5120 halves = 10240 bytes per matrix per stage
#define MOFF ((uint32_t)TILE_HALF * 2)   // matrix offset in bytes
#define NSTAGE 3

// GEMM1: H = silu(Xg @ Wg^T) * (Xg @ Wu^T); fp16 operands, fp32 accum
// warps 2(m) x 4(n), warp tile 64x32
__global__ __launch_bounds__(256) void gemm1_kernel() {
    int e = blockIdx.z;
    int cnt = g_cnt[e];
    int m0 = blockIdx.y * BM;
    if (m0 >= cnt) return;
    int n0 = blockIdx.x * BN;

    extern __shared__ __half sm[];
    __shared__ int stok[BM];
    int tid = threadIdx.x;
    if (tid < BM) { int r = m0 + tid; stok[tid] = (r < cnt) ? g_tok[e * MAXR + r] : 0; }
    __syncthreads();

    const uint32_t SS = 3u * MOFF;  // stage stride bytes (A, Bg, Bu)
    uint32_t sb = su32(sm);
    int rr = tid >> 1;
    int ko = (tid & 1) * 16;
    const __half* srcA = g_X_h  + (size_t)stok[rr] * DIM + ko;
    const __half* srcG = g_Wg_h + ((size_t)e * FF + n0 + rr) * DIM + ko;
    const __half* srcU = g_Wu_h + ((size_t)e * FF + n0 + rr) * DIM + ko;
    uint32_t dst0 = sb + (uint32_t)(rr * LDH + ko) * 2;

#define G1_ISSUE(s, kt) do {                                                     \
        uint32_t d_ = dst0 + (uint32_t)(s) * SS;                                 \
        int kh_ = (kt) * BK;                                                     \
        cp16(d_,              srcA + kh_); cp16(d_ + 16,            srcA + kh_ + 8); \
        cp16(d_ + MOFF,       srcG + kh_); cp16(d_ + MOFF + 16,     srcG + kh_ + 8); \
        cp16(d_ + 2 * MOFF,   srcU + kh_); cp16(d_ + 2 * MOFF + 16, srcU + kh_ + 8); \
    } while (0)

    int lane = tid & 31, wid = tid >> 5;
    int g = lane >> 2, t4 = lane & 3;
    int wm = wid & 1, wn = wid >> 1;   // 2 x 4 warp grid

    int aoff[4], boff[4];
#pragma unroll
    for (int im = 0; im < 4; im++) aoff[im] = (wm * 64 + im * 16 + g) * LDH + 2 * t4;
#pragma unroll
    for (int jn = 0; jn < 4; jn++) boff[jn] = (wn * 32 + jn * 8 + g) * LDH + 2 * t4;

    float ag[4][4][4], au[4][4][4];
#pragma unroll
    for (int i = 0; i < 4; i++)
#pragma unroll
        for (int j = 0; j < 4; j++)
#pragma unroll
            for (int c = 0; c < 4; c++) { ag[i][j][c] = 0.f; au[i][j][c] = 0.f; }

    G1_ISSUE(0, 0); CP_COMMIT();
    G1_ISSUE(1, 1); CP_COMMIT();

    const int NK = DIM / BK;  // 24
    for (int kt = 0; kt < NK; kt++) {
        CP_WAIT_1();
        __syncthreads();
        if (kt + 2 < NK) G1_ISSUE((kt + 2) % NSTAGE, kt + 2);
        CP_COMMIT();
        const __half* sA = sm + (kt % NSTAGE) * (3 * TILE_HALF);
        const __half* sG = sA + TILE_HALF;
        const __half* sU = sG + TILE_HALF;
#pragma unroll
        for (int km = 0; km < 2; km++) {
            int kb = km * 16;
            uint32_t a[4][4];
#pragma unroll
            for (int im = 0; im < 4; im++) {
                a[im][0] = *(const uint32_t*)&sA[aoff[im] + kb];
                a[im][1] = *(const uint32_t*)&sA[aoff[im] + 8 * LDH + kb];
                a[im][2] = *(const uint32_t*)&sA[aoff[im] + kb + 8];
                a[im][3] = *(const uint32_t*)&sA[aoff[im] + 8 * LDH + kb + 8];
            }
#pragma unroll
            for (int jn = 0; jn < 4; jn++) {
                uint32_t g0 = *(const uint32_t*)&sG[boff[jn] + kb];
                uint32_t g1 = *(const uint32_t*)&sG[boff[jn] + kb + 8];
                uint32_t u0 = *(const uint32_t*)&sU[boff[jn] + kb];
                uint32_t u1 = *(const uint32_t*)&sU[boff[jn] + kb + 8];
#pragma unroll
                for (int im = 0; im < 4; im++) {
                    MMA_F16(ag[im][jn], a[im], g0, g1);
                    MMA_F16(au[im][jn], a[im], u0, u1);
                }
            }
        }
    }

    // epilogue: h = silu(g) * u, store fp16 H
#pragma unroll
    for (int im = 0; im < 4; im++) {
#pragma unroll
        for (int jn = 0; jn < 4; jn++) {
            int rl  = wm * 64 + im * 16 + g;
            int col = n0 + wn * 32 + jn * 8 + t4 * 2;
            size_t b0i = (size_t)(e * MAXR + m0 + rl) * FF + col;
            size_t b1i = (size_t)(e * MAXR + m0 + rl + 8) * FF + col;
            float gg, uu, h0x, h0y, h1x, h1y;
            gg = ag[im][jn][0]; uu = au[im][jn][0]; h0x = gg / (1.f + expf(-gg)) * uu;
            gg = ag[im][jn][1]; uu = au[im][jn][1]; h0y = gg / (1.f + expf(-gg)) * uu;
            gg = ag[im][jn][2]; uu = au[im][jn][2]; h1x = gg / (1.f + expf(-gg)) * uu;
            gg = ag[im][jn][3]; uu = au[im][jn][3]; h1y = gg / (1.f + expf(-gg)) * uu;
            *(__half2*)&g_H_h[b0i] = __floats2half2_rn(h0x, h0y);
            *(__half2*)&g_H_h[b1i] = __floats2half2_rn(h1x, h1y);
        }
    }
}

// GEMM2: Y = H @ Wo^T; fp16 operands, fp32 accum; 2 CTAs/SM target
__global__ __launch_bounds__(256, 2) void gemm2_kernel() {
    int e = blockIdx.z;
    int cnt = g_cnt[e];
    int m0 = blockIdx.y * BM;
    if (m0 >= cnt) return;
    int n0 = blockIdx.x * BN;

    extern __shared__ __half sm[];
    int tid = threadIdx.x;

    const uint32_t SS = 2u * MOFF;  // stage stride bytes (A, B)
    uint32_t sb = su32(sm);
    int rr = tid >> 1;
    int ko = (tid & 1) * 16;
    const __half* srcA = g_H_h  + ((size_t)(e * MAXR + m0 + rr)) * FF + ko;
    const __half* srcB = g_Wo_h + ((size_t)e * DIM + n0 + rr) * FF + ko;
    uint32_t dst0 = sb + (uint32_t)(rr * LDH + ko) * 2;

#define G2_ISSUE(s, kt) do {                                                     \
        uint32_t d_ = dst0 + (uint32_t)(s) * SS;                                 \
        int kh_ = (kt) * BK;                                                     \
        cp16(d_,          srcA + kh_); cp16(d_ + 16,        srcA + kh_ + 8);     \
        cp16(d_ + MOFF,   srcB + kh_); cp16(d_ + MOFF + 16, srcB + kh_ + 8);     \
    } while (0)

    int lane = tid & 31, wid = tid >> 5;
    int g = lane >> 2, t4 = lane & 3;
    int wm = wid & 1, wn = wid >> 1;

    int aoff[4], boff[4];
#pragma unroll
    for (int im = 0; im < 4; im++) aoff[im] = (wm * 64 + im * 16 + g) * LDH + 2 * t4;
#pragma unroll
    for (int jn = 0; jn < 4; jn++) boff[jn] = (wn * 32 + jn * 8 + g) * LDH + 2 * t4;

    float acc[4][4][4];
#pragma unroll
    for (int i = 0; i < 4; i++)
#pragma unroll
        for (int j = 0; j < 4; j++)
#pragma unroll
            for (int c = 0; c < 4; c++) acc[i][j][c] = 0.f;

    G2_ISSUE(0, 0); CP_COMMIT();
    G2_ISSUE(1, 1); CP_COMMIT();

    const int NK = FF / BK;  // 96
    for (int kt = 0; kt < NK; kt++) {
        CP_WAIT_1();
        __syncthreads();
        if (kt + 2 < NK) G2_ISSUE((kt + 2) % NSTAGE, kt + 2);
        CP_COMMIT();
        const __half* sA = sm + (kt % NSTAGE) * (2 * TILE_HALF);
        const __half* sB = sA + TILE_HALF;
#pragma unroll
        for (int km = 0; km < 2; km++) {
            int kb = km * 16;
            uint32_t a[4][4];
#pragma unroll
            for (int im = 0; im < 4; im++) {
                a[im][0] = *(const uint32_t*)&sA[aoff[im] + kb];
                a[im][1] = *(const uint32_t*)&sA[aoff[im] + 8 * LDH + kb];
                a[im][2] = *(const uint32_t*)&sA[aoff[im] + kb + 8];
                a[im][3] = *(const uint32_t*)&sA[aoff[im] + 8 * LDH + kb + 8];
            }
#pragma unroll
            for (int jn = 0; jn < 4; jn++) {
                uint32_t b0 = *(const uint32_t*)&sB[boff[jn] + kb];
                uint32_t b1 = *(const uint32_t*)&sB[boff[jn] + kb + 8];
#pragma unroll
                for (int im = 0; im < 4; im++) MMA_F16(acc[im][jn], a[im], b0, b1);
            }
        }
    }

#pragma unroll
    for (int im = 0; im < 4; im++) {
#pragma unroll
        for (int jn = 0; jn < 4; jn++) {
            int rl  = wm * 64 + im * 16 + g;
            int col = n0 + wn * 32 + jn * 8 + t4 * 2;
            size_t b0i = (size_t)(e * MAXR + m0 + rl) * DIM + col;
            size_t b1i = (size_t)(e * MAXR + m0 + rl + 8) * DIM + col;
            *(float2*)&g_Y[b0i] = make_float2(acc[im][jn][0], acc[im][jn][1]);
            *(float2*)&g_Y[b1i] = make_float2(acc[im][jn][2], acc[im][jn][3]);
        }
    }
}

// ---------------- combine ----------------
__global__ void combine_kernel(float* __restrict__ out) {
    int gi = blockIdx.x * 256 + threadIdx.x;
    int t = gi / (DIM / 4);
    int c = (gi % (DIM / 4)) * 4;
    float w0 = g_wk[t * 2], w1 = g_wk[t * 2 + 1];
    float4 acc = make_float4(0.f, 0.f, 0.f, 0.f);
    if (w0 > 0.f) {
        const float4 y = *(const float4*)&g_Y[(size_t)g_rowidx[t * 2] * DIM + c];
        acc.x = w0 * y.x; acc.y = w0 * y.y; acc.z = w0 * y.z; acc.w = w0 * y.w;
    }
    if (w1 > 0.f) {
        const float4 y = *(const float4*)&g_Y[(size_t)g_rowidx[t * 2 + 1] * DIM + c];
        acc.x += w1 * y.x; acc.y += w1 * y.y; acc.z += w1 * y.z; acc.w += w1 * y.w;
    }
    *(float4*)(out + (size_t)gi * 4) = acc;
}

// ---------------- finalize ----------------
__global__ void finalize_kernel(float* __restrict__ out, int out_size) {
    if (threadIdx.x == 0 && out_size > T_TOK * DIM) {
        float lb = 0.f;
        for (int e = 0; e < NE; e++) {
            float f = (float)g_cnta[e] / (float)(T_TOK * 2);
            float P = g_psum[e] / (float)T_TOK;
            lb += f * P;
        }
        lb *= (float)NE;
        float z = g_zsum / (float)T_TOK;
        out[T_TOK * DIM] = 0.01f * lb + 0.001f * z;
    }
}

// ---------------- launch ----------------
extern "C" void kernel_launch(void* const* d_in, const int* in_sizes, int n_in,
                              void* d_out, int out_size) {
    (void)in_sizes; (void)n_in;
    const float* x   = (const float*)d_in[0];
    const float* wg  = (const float*)d_in[1];
    const float* wig = (const float*)d_in[2];
    const float* wiu = (const float*)d_in[3];
    const float* wo  = (const float*)d_in[4];
    float* out = (float*)d_out;

    const int G1_SMEM = NSTAGE * 3 * TILE_HALF * 2;  // 92160 bytes
    const int G2_SMEM = NSTAGE * 2 * TILE_HALF * 2;  // 61440 bytes
    cudaFuncSetAttribute(gemm1_kernel, cudaFuncAttributeMaxDynamicSharedMemorySize, G1_SMEM);
    cudaFuncSetAttribute(gemm2_kernel, cudaFuncAttributeMaxDynamicSharedMemorySize, G2_SMEM);

    const int NW8 = (NE * FF * DIM) / 8;   // 2359296
    const int NX8 = (T_TOK * DIM) / 8;     // 786432

    init_kernel<<<1, 32>>>();
    cvt_half_kernel<<<(NX8 + 255) / 256, 256>>>(x, 0, NX8);
    cvt_half_kernel<<<(NW8 + 255) / 256, 256>>>(wig, 1, NW8);
    cvt_half_kernel<<<(NW8 + 255) / 256, 256>>>(wiu, 2, NW8);
    cvt_half_kernel<<<(NW8 + 255) / 256, 256>>>(wo, 3, NW8);
    router_kernel<<<T_TOK / 8, 256>>>(x, wg);
    scan_kernel<<<NE, 256>>>();
    gemm1_kernel<<<dim3(FF / BN, MAXR / BM, NE), 256, G1_SMEM>>>();
    gemm2_kernel<<<dim3(DIM / BN, MAXR / BM, NE), 256, G2_SMEM>>>();
    combine_kernel<<<(T_TOK * DIM / 4) / 256, 256>>>(out);
    finalize_kernel<<<1, 1>>>(out, out_size);
}

// round 6
// speedup vs baseline: 2.0879x; 1.1465x over previous
#include <cuda_runtime.h>
#include <cuda_fp16.h>
#include <math.h>
#include <stdint.h>

#define T_TOK 8192
#define DIM   768
#define FF    3072
#define NE    8
#define CAP   2560
#define MAXR  5120   // 2*CAP, max gathered rows per expert

// ---------------- static device scratch ----------------
__device__ __half g_Wg_h[(size_t)NE * FF * DIM];
__device__ __half g_Wu_h[(size_t)NE * FF * DIM];
__device__ __half g_Wo_h[(size_t)NE * DIM * FF];
__device__ __half g_X_h[(size_t)T_TOK * DIM];
__device__ __half g_H_h[(size_t)NE * MAXR * FF];
__device__ float  g_Y[(size_t)NE * MAXR * DIM];
__device__ int    g_tok[NE * MAXR];
__device__ int    g_topk[T_TOK * 2];
__device__ float  g_topp[T_TOK * 2];
__device__ int    g_rowidx[T_TOK * 2];
__device__ float  g_wk[T_TOK * 2];
__device__ int    g_cnt[NE];
__device__ int    g_cnta[NE];
__device__ float  g_psum[NE];
__device__ float  g_zsum;

// ---------------- helpers ----------------
__device__ __forceinline__ uint32_t su32(const void* p) {
    uint32_t a;
    asm("{ .reg .u64 t; cvta.to.shared.u64 t, %1; cvt.u32.u64 %0, t; }" : "=r"(a) : "l"(p));
    return a;
}
__device__ __forceinline__ void cp16(uint32_t dst, const void* src) {
    asm volatile("cp.async.cg.shared.global [%0], [%1], 16;" :: "r"(dst), "l"(src) : "memory");
}
#define CP_COMMIT() asm volatile("cp.async.commit_group;" ::: "memory")
#define CP_WAIT_1() asm volatile("cp.async.wait_group 1;" ::: "memory")

#define MMA_F16(D, A, B0, B1)                                                    \
    asm volatile(                                                                \
        "mma.sync.aligned.m16n8k16.row.col.f32.f16.f16.f32 "                     \
        "{%0,%1,%2,%3}, {%4,%5,%6,%7}, {%8,%9}, {%0,%1,%2,%3};\n"                \
        : "+f"((D)[0]), "+f"((D)[1]), "+f"((D)[2]), "+f"((D)[3])                 \
        : "r"((A)[0]), "r"((A)[1]), "r"((A)[2]), "r"((A)[3]), "r"(B0), "r"(B1))

#define LDSM4(R, addr)                                                           \
    asm volatile("ldmatrix.sync.aligned.m8n8.x4.shared.b16 {%0,%1,%2,%3}, [%4];" \
        : "=r"((R)[0]), "=r"((R)[1]), "=r"((R)[2]), "=r"((R)[3]) : "r"(addr))

// ---------------- init ----------------
__global__ void init_kernel() {
    int tid = threadIdx.x;
    if (tid < NE) { g_psum[tid] = 0.f; g_cnta[tid] = 0; }
    if (tid == 0) g_zsum = 0.f;
}

// ---------------- fp32 -> fp16 conversion pass ----------------
__global__ void cvt_half_kernel(const float* __restrict__ s, int which, int n8) {
    int i = blockIdx.x * blockDim.x + threadIdx.x;
    if (i >= n8) return;
    __half* d = (which == 0) ? g_X_h : (which == 1) ? g_Wg_h : (which == 2) ? g_Wu_h : g_Wo_h;
    float4 v0 = ((const float4*)s)[2 * i];
    float4 v1 = ((const float4*)s)[2 * i + 1];
    __half2 h0 = __floats2half2_rn(v0.x, v0.y);
    __half2 h1 = __floats2half2_rn(v0.z, v0.w);
    __half2 h2 = __floats2half2_rn(v1.x, v1.y);
    __half2 h3 = __floats2half2_rn(v1.z, v1.w);
    uint4 o;
    o.x = *(const uint32_t*)&h0; o.y = *(const uint32_t*)&h1;
    o.z = *(const uint32_t*)&h2; o.w = *(const uint32_t*)&h3;
    ((uint4*)d)[i] = o;
}

// ---------------- router ----------------
__global__ void router_kernel(const float* __restrict__ x, const float* __restrict__ wg) {
    __shared__ float sg[NE * DIM];
    __shared__ float shp[NE];
    __shared__ int   shc[NE];
    __shared__ float shz;
    int tid = threadIdx.x;
    for (int i = tid; i < NE * DIM; i += 256) sg[i] = wg[i];
    if (tid < NE) { shp[tid] = 0.f; shc[tid] = 0; }
    if (tid == 0) shz = 0.f;
    __syncthreads();

    int w = tid >> 5, lane = tid & 31;
    int t = blockIdx.x * 8 + w;
    const float* xt = x + (size_t)t * DIM;
    float acc[NE];
#pragma unroll
    for (int e = 0; e < NE; e++) acc[e] = 0.f;
    for (int j = lane; j < DIM; j += 32) {
        float xv = xt[j];
#pragma unroll
        for (int e = 0; e < NE; e++) acc[e] += xv * sg[e * DIM + j];
    }
#pragma unroll
    for (int o = 16; o > 0; o >>= 1) {
#pragma unroll
        for (int e = 0; e < NE; e++) acc[e] += __shfl_xor_sync(0xffffffffu, acc[e], o);
    }
    if (lane == 0) {
        float m = acc[0];
#pragma unroll
        for (int e = 1; e < NE; e++) m = fmaxf(m, acc[e]);
        float p[NE]; float s = 0.f;
#pragma unroll
        for (int e = 0; e < NE; e++) { p[e] = expf(acc[e] - m); s += p[e]; }
        float inv = 1.f / s;
#pragma unroll
        for (int e = 0; e < NE; e++) p[e] *= inv;
        float lse = m + logf(s);
        int i0 = 0; float b0 = p[0];
#pragma unroll
        for (int e = 1; e < NE; e++) if (p[e] > b0) { b0 = p[e]; i0 = e; }
        int i1 = -1; float b1 = -1.f;
#pragma unroll
        for (int e = 0; e < NE; e++) if (e != i0 && p[e] > b1) { b1 = p[e]; i1 = e; }
        float invs = 1.f / (b0 + b1);
        g_topk[t * 2] = i0; g_topk[t * 2 + 1] = i1;
        g_topp[t * 2] = b0 * invs; g_topp[t * 2 + 1] = b1 * invs;
#pragma unroll
        for (int e = 0; e < NE; e++) atomicAdd(&shp[e], p[e]);
        atomicAdd(&shc[i0], 1);
        atomicAdd(&shc[i1], 1);
        atomicAdd(&shz, lse * lse);
    }
    __syncthreads();
    if (tid < NE) { atomicAdd(&g_psum[tid], shp[tid]); atomicAdd(&g_cnta[tid], shc[tid]); }
    if (tid == 0) atomicAdd(&g_zsum, shz);
}

// ---------------- scan ----------------
__global__ void scan_kernel() {
    int e = blockIdx.x;
    int tid = threadIdx.x;
    int w = tid >> 5, lane = tid & 31;
    unsigned ltm = (1u << lane) - 1u;
    __shared__ int sw0[8], sw1[8], sws[8];
    __shared__ int base0, base1, baseS;
    if (tid == 0) { base0 = 0; base1 = 0; baseS = 0; }
    __syncthreads();
    for (int b = 0; b < T_TOK; b += 256) {
        int t = b + tid;
        int i0 = g_topk[t * 2], i1 = g_topk[t * 2 + 1];
        int a0 = (i0 == e) ? 1 : 0;
        int a1 = (i1 == e) ? 1 : 0;
        unsigned m0b = __ballot_sync(0xffffffffu, a0);
        unsigned m1b = __ballot_sync(0xffffffffu, a1);
        if (lane == 0) { sw0[w] = __popc(m0b); sw1[w] = __popc(m1b); }
        __syncthreads();
        int off0 = base0, off1 = base1;
        for (int j = 0; j < w; j++) { off0 += sw0[j]; off1 += sw1[j]; }
        int r0 = off0 + __popc(m0b & ltm);
        int r1 = off1 + __popc(m1b & ltm);
        int k0 = a0 && (r0 < CAP);
        int k1 = a1 && (r1 < CAP);
        int sel = (k0 || k1) ? 1 : 0;
        unsigned msb = __ballot_sync(0xffffffffu, sel);
        if (lane == 0) sws[w] = __popc(msb);
        __syncthreads();
        int offS = baseS;
        for (int j = 0; j < w; j++) offS += sws[j];
        int pos = offS + __popc(msb & ltm);
        if (sel) g_tok[e * MAXR + pos] = t;
        if (a0) { g_wk[t * 2]     = k0 ? g_topp[t * 2]     : 0.f; g_rowidx[t * 2]     = k0 ? (e * MAXR + pos) : 0; }
        if (a1) { g_wk[t * 2 + 1] = k1 ? g_topp[t * 2 + 1] : 0.f; g_rowidx[t * 2 + 1] = k1 ? (e * MAXR + pos) : 0; }
        __syncthreads();
        if (tid == 0) {
            int t0 = 0, t1 = 0, ts = 0;
            for (int j = 0; j < 8; j++) { t0 += sw0[j]; t1 += sw1[j]; ts += sws[j]; }
            base0 += t0; base1 += t1; baseS += ts;
        }
        __syncthreads();
    }
    if (tid == 0) g_cnt[e] = baseS;
}

// ---------------- GEMM config ----------------
#define BM 128
#define BK 32                  // halves per k-tile (2 x k16 mma steps)
#define LDH 40                 // halves per smem row (32 data + 8 pad), LDSM-conflict-free
#define G1_STAGE 20480u        // bytes: A(128x40x2=10240) + G(64x40x2=5120) + U(5120)
#define G1_GOFF  10240u
#define G1_UOFF  15360u
#define G2_STAGE 15360u        // bytes: A(10240) + B(5120)
#define G2_BOFF  10240u
#define NSTAGE 3

// GEMM1: H = silu(Xg @ Wg^T) * (Xg @ Wu^T); BM=128, BN=64 (per matrix)
// warps 4(m) x 2(n), warp tile 32x32, LDSM fragments, 2 CTAs/SM
__global__ __launch_bounds__(256, 2) void gemm1_kernel() {
    int e = blockIdx.z;
    int cnt = g_cnt[e];
    int m0 = blockIdx.y * BM;
    if (m0 >= cnt) return;
    int n0 = blockIdx.x * 64;

    extern __shared__ __half sm[];
    __shared__ int stok[BM];
    int tid = threadIdx.x;
    if (tid < BM) { int r = m0 + tid; stok[tid] = (r < cnt) ? g_tok[e * MAXR + r] : 0; }
    __syncthreads();

    uint32_t sb = su32(sm);
    int rr = tid >> 1;
    int ko = (tid & 1) * 16;
    const __half* srcA = g_X_h + (size_t)stok[rr] * DIM + ko;
    uint32_t dstA = sb + (uint32_t)(rr * LDH + ko) * 2;
    int bro = (tid & 127) >> 1;   // 0..63
    const __half* srcB = ((tid < 128) ? g_Wg_h : g_Wu_h) + ((size_t)e * FF + n0 + bro) * DIM + ko;
    uint32_t dstB = sb + ((tid < 128) ? G1_GOFF : G1_UOFF) + (uint32_t)(bro * LDH + ko) * 2;

#define G1_ISSUE(s, kt) do {                                           \
        uint32_t b_ = (uint32_t)(s) * G1_STAGE;                        \
        int kh_ = (kt) * BK;                                           \
        cp16(dstA + b_, srcA + kh_); cp16(dstA + b_ + 16, srcA + kh_ + 8); \
        cp16(dstB + b_, srcB + kh_); cp16(dstB + b_ + 16, srcB + kh_ + 8); \
    } while (0)

    int lane = tid & 31, wid = tid >> 5;
    int g = lane >> 2, t4 = lane & 3;
    int wm = wid & 3, wn = wid >> 2;   // 4 x 2 warp grid

    // LDSM lane-address offsets (bytes from stage base)
    uint32_t offA[2], offB[2];
#pragma unroll
    for (int im = 0; im < 2; im++)
        offA[im] = (uint32_t)((wm * 32 + im * 16 + (lane & 15)) * LDH + (lane >> 4) * 8) * 2;
#pragma unroll
    for (int p = 0; p < 2; p++)
        offB[p] = G1_GOFF + (uint32_t)((wn * 32 + (p * 2 + (lane >> 4)) * 8 + (lane & 7)) * LDH
                                       + ((lane >> 3) & 1) * 8) * 2;

    float ag[2][4][4], au[2][4][4];
#pragma unroll
    for (int i = 0; i < 2; i++)
#pragma unroll
        for (int j = 0; j < 4; j++)
#pragma unroll
            for (int c = 0; c < 4; c++) { ag[i][j][c] = 0.f; au[i][j][c] = 0.f; }

    G1_ISSUE(0, 0); CP_COMMIT();
    G1_ISSUE(1, 1); CP_COMMIT();

    const int NK = DIM / BK;  // 24
    for (int kt = 0; kt < NK; kt++) {
        CP_WAIT_1();
        __syncthreads();
        if (kt + 2 < NK) G1_ISSUE((kt + 2) % NSTAGE, kt + 2);
        CP_COMMIT();
        uint32_t stb = sb + (uint32_t)(kt % NSTAGE) * G1_STAGE;
#pragma unroll
        for (int km = 0; km < 2; km++) {
            uint32_t kmo = km * 32;
            uint32_t a[2][4], gq[2][4], uq[2][4];
            LDSM4(a[0], stb + offA[0] + kmo);
            LDSM4(a[1], stb + offA[1] + kmo);
            LDSM4(gq[0], stb + offB[0] + kmo);
            LDSM4(gq[1], stb + offB[1] + kmo);
            LDSM4(uq[0], stb + offB[0] + (G1_UOFF - G1_GOFF) + kmo);
            LDSM4(uq[1], stb + offB[1] + (G1_UOFF - G1_GOFF) + kmo);
#pragma unroll
            for (int p = 0; p < 2; p++) {
#pragma unroll
                for (int s = 0; s < 2; s++) {
                    int jn = p * 2 + s;
#pragma unroll
                    for (int im = 0; im < 2; im++) {
                        MMA_F16(ag[im][jn], a[im], gq[p][s * 2], gq[p][s * 2 + 1]);
                        MMA_F16(au[im][jn], a[im], uq[p][s * 2], uq[p][s * 2 + 1]);
                    }
                }
            }
        }
    }

    // epilogue: h = silu(g) * u, store fp16 H
#pragma unroll
    for (int im = 0; im < 2; im++) {
#pragma unroll
        for (int jn = 0; jn < 4; jn++) {
            int rl  = wm * 32 + im * 16 + g;
            int col = n0 + wn * 32 + jn * 8 + t4 * 2;
            size_t b0i = (size_t)(e * MAXR + m0 + rl) * FF + col;
            size_t b1i = (size_t)(e * MAXR + m0 + rl + 8) * FF + col;
            float gg, uu, h0x, h0y, h1x, h1y;
            gg = ag[im][jn][0]; uu = au[im][jn][0]; h0x = gg / (1.f + expf(-gg)) * uu;
            gg = ag[im][jn][1]; uu = au[im][jn][1]; h0y = gg / (1.f + expf(-gg)) * uu;
            gg = ag[im][jn][2]; uu = au[im][jn][2]; h1x = gg / (1.f + expf(-gg)) * uu;
            gg = ag[im][jn][3]; uu = au[im][jn][3]; h1y = gg / (1.f + expf(-gg)) * uu;
            *(__half2*)&g_H_h[b0i] = __floats2half2_rn(h0x, h0y);
            *(__half2*)&g_H_h[b1i] = __floats2half2_rn(h1x, h1y);
        }
    }
}

// GEMM2: Y = H @ Wo^T; BM=128, BN=64, warps 4x2, warp tile 32x32, 2 CTAs/SM
__global__ __launch_bounds__(256, 2) void gemm2_kernel() {
    int e = blockIdx.z;
    int cnt = g_cnt[e];
    int m0 = blockIdx.y * BM;
    if (m0 >= cnt) return;
    int n0 = blockIdx.x * 64;

    extern __shared__ __half sm[];
    int tid = threadIdx.x;
    uint32_t sb = su32(sm);
    int rr = tid >> 1;
    int ko = (tid & 1) * 16;
    const __half* srcA = g_H_h + (size_t)(e * MAXR + m0 + rr) * FF + ko;
    uint32_t dstA = sb + (uint32_t)(rr * LDH + ko) * 2;
    int bro = tid >> 1;  // only tid<128 uses it (rows 0..63)
    const __half* srcB = g_Wo_h + ((size_t)e * DIM + n0 + bro) * FF + ko;
    uint32_t dstB = sb + G2_BOFF + (uint32_t)(bro * LDH + ko) * 2;

#define G2_ISSUE(s, kt) do {                                           \
        uint32_t b_ = (uint32_t)(s) * G2_STAGE;                        \
        int kh_ = (kt) * BK;                                           \
        cp16(dstA + b_, srcA + kh_); cp16(dstA + b_ + 16, srcA + kh_ + 8); \
        if (tid < 128) { cp16(dstB + b_, srcB + kh_); cp16(dstB + b_ + 16, srcB + kh_ + 8); } \
    } while (0)

    int lane = tid & 31, wid = tid >> 5;
    int g = lane >> 2, t4 = lane & 3;
    int wm = wid & 3, wn = wid >> 2;

    uint32_t offA[2], offB[2];
#pragma unroll
    for (int im = 0; im < 2; im++)
        offA[im] = (uint32_t)((wm * 32 + im * 16 + (lane & 15)) * LDH + (lane >> 4) * 8) * 2;
#pragma unroll
    for (int p = 0; p < 2; p++)
        offB[p] = G2_BOFF + (uint32_t)((wn * 32 + (p * 2 + (lane >> 4)) * 8 + (lane & 7)) * LDH
                                       + ((lane >> 3) & 1) * 8) * 2;

    float acc[2][4][4];
#pragma unroll
    for (int i = 0; i < 2; i++)
#pragma unroll
        for (int j = 0; j < 4; j++)
#pragma unroll
            for (int c = 0; c < 4; c++) acc[i][j][c] = 0.f;

    G2_ISSUE(0, 0); CP_COMMIT();
    G2_ISSUE(1, 1); CP_COMMIT();

    const int NK = FF / BK;  // 96
    for (int kt = 0; kt < NK; kt++) {
        CP_WAIT_1();
        __syncthreads();
        if (kt + 2 < NK) G2_ISSUE((kt + 2) % NSTAGE, kt + 2);
        CP_COMMIT();
        uint32_t stb = sb + (uint32_t)(kt % NSTAGE) * G2_STAGE;
#pragma unroll
        for (int km = 0; km < 2; km++) {
            uint32_t kmo = km * 32;
            uint32_t a[2][4], bq[2][4];
            LDSM4(a[0], stb + offA[0] + kmo);
            LDSM4(a[1], stb + offA[1] + kmo);
            LDSM4(bq[0], stb + offB[0] + kmo);
            LDSM4(bq[1], stb + offB[1] + kmo);
#pragma unroll
            for (int p = 0; p < 2; p++) {
#pragma unroll
                for (int s = 0; s < 2; s++) {
                    int jn = p * 2 + s;
#pragma unroll
                    for (int im = 0; im < 2; im++)
                        MMA_F16(acc[im][jn], a[im], bq[p][s * 2], bq[p][s * 2 + 1]);
                }
            }
        }
    }

#pragma unroll
    for (int im = 0; im < 2; im++) {
#pragma unroll
        for (int jn = 0; jn < 4; jn++) {
            int rl  = wm * 32 + im * 16 + g;
            int col = n0 + wn * 32 + jn * 8 + t4 * 2;
            size_t b0i = (size_t)(e * MAXR + m0 + rl) * DIM + col;
            size_t b1i = (size_t)(e * MAXR + m0 + rl + 8) * DIM + col;
            *(float2*)&g_Y[b0i] = make_float2(acc[im][jn][0], acc[im][jn][1]);
            *(float2*)&g_Y[b1i] = make_float2(acc[im][jn][2], acc[im][jn][3]);
        }
    }
}

// ---------------- combine ----------------
__global__ void combine_kernel(float* __restrict__ out) {
    int gi = blockIdx.x * 256 + threadIdx.x;
    int t = gi / (DIM / 4);
    int c = (gi % (DIM / 4)) * 4;
    float w0 = g_wk[t * 2], w1 = g_wk[t * 2 + 1];
    float4 acc = make_float4(0.f, 0.f, 0.f, 0.f);
    if (w0 > 0.f) {
        const float4 y = *(const float4*)&g_Y[(size_t)g_rowidx[t * 2] * DIM + c];
        acc.x = w0 * y.x; acc.y = w0 * y.y; acc.z = w0 * y.z; acc.w = w0 * y.w;
    }
    if (w1 > 0.f) {
        const float4 y = *(const float4*)&g_Y[(size_t)g_rowidx[t * 2 + 1] * DIM + c];
        acc.x += w1 * y.x; acc.y += w1 * y.y; acc.z += w1 * y.z; acc.w += w1 * y.w;
    }
    *(float4*)(out + (size_t)gi * 4) = acc;
}

// ---------------- finalize ----------------
__global__ void finalize_kernel(float* __restrict__ out, int out_size) {
    if (threadIdx.x == 0 && out_size > T_TOK * DIM) {
        float lb = 0.f;
        for (int e = 0; e < NE; e++) {
            float f = (float)g_cnta[e] / (float)(T_TOK * 2);
            float P = g_psum[e] / (float)T_TOK;
            lb += f * P;
        }
        lb *= (float)NE;
        float z = g_zsum / (float)T_TOK;
        out[T_TOK * DIM] = 0.01f * lb + 0.001f * z;
    }
}

// ---------------- launch ----------------
extern "C" void kernel_launch(void* const* d_in, const int* in_sizes, int n_in,
                              void* d_out, int out_size) {
    (void)in_sizes; (void)n_in;
    const float* x   = (const float*)d_in[0];
    const float* wg  = (const float*)d_in[1];
    const float* wig = (const float*)d_in[2];
    const float* wiu = (const float*)d_in[3];
    const float* wo  = (const float*)d_in[4];
    float* out = (float*)d_out;

    const int G1_SMEM = NSTAGE * G1_STAGE;  // 61440 bytes
    const int G2_SMEM = NSTAGE * G2_STAGE;  // 46080 bytes
    cudaFuncSetAttribute(gemm1_kernel, cudaFuncAttributeMaxDynamicSharedMemorySize, G1_SMEM);
    cudaFuncSetAttribute(gemm2_kernel, cudaFuncAttributeMaxDynamicSharedMemorySize, G2_SMEM);

    const int NW8 = (NE * FF * DIM) / 8;   // 2359296
    const int NX8 = (T_TOK * DIM) / 8;     // 786432

    init_kernel<<<1, 32>>>();
    cvt_half_kernel<<<(NX8 + 255) / 256, 256>>>(x, 0, NX8);
    cvt_half_kernel<<<(NW8 + 255) / 256, 256>>>(wig, 1, NW8);
    cvt_half_kernel<<<(NW8 + 255) / 256, 256>>>(wiu, 2, NW8);
    cvt_half_kernel<<<(NW8 + 255) / 256, 256>>>(wo, 3, NW8);
    router_kernel<<<T_TOK / 8, 256>>>(x, wg);
    scan_kernel<<<NE, 256>>>();
    gemm1_kernel<<<dim3(FF / 64, MAXR / BM, NE), 256, G1_SMEM>>>();
    gemm2_kernel<<<dim3(DIM / 64, MAXR / BM, NE), 256, G2_SMEM>>>();
    combine_kernel<<<(T_TOK * DIM / 4) / 256, 256>>>(out);
    finalize_kernel<<<1, 1>>>(out, out_size);
}

// round 7
// speedup vs baseline: 2.0962x; 1.0039x over previous
#include <cuda_runtime.h>
#include <cuda_fp16.h>
#include <math.h>
#include <stdint.h>

#define T_TOK 8192
#define DIM   768
#define FF    3072
#define NE    8
#define CAP   2560
#define MAXR  5120   // 2*CAP, max gathered rows per expert

// ---------------- static device scratch ----------------
__device__ __half g_Wg_h[(size_t)NE * FF * DIM];
__device__ __half g_Wu_h[(size_t)NE * FF * DIM];
__device__ __half g_Wo_h[(size_t)NE * DIM * FF];
__device__ __half g_X_h[(size_t)T_TOK * DIM];
__device__ __half g_H_h[(size_t)NE * MAXR * FF];
__device__ float  g_Y[(size_t)NE * MAXR * DIM];
__device__ int    g_tok[NE * MAXR];
__device__ int    g_topk[T_TOK * 2];
__device__ float  g_topp[T_TOK * 2];
__device__ int    g_rowidx[T_TOK * 2];
__device__ float  g_wk[T_TOK * 2];
__device__ int    g_cnt[NE];
__device__ int    g_cnta[NE];
__device__ float  g_psum[NE];
__device__ float  g_zsum;

// ---------------- helpers ----------------
__device__ __forceinline__ uint32_t su32(const void* p) {
    uint32_t a;
    asm("{ .reg .u64 t; cvta.to.shared.u64 t, %1; cvt.u32.u64 %0, t; }" : "=r"(a) : "l"(p));
    return a;
}
__device__ __forceinline__ void cp16(uint32_t dst, const void* src) {
    asm volatile("cp.async.cg.shared.global [%0], [%1], 16;" :: "r"(dst), "l"(src) : "memory");
}
#define CP_COMMIT() asm volatile("cp.async.commit_group;" ::: "memory")
#define CP_WAIT_2() asm volatile("cp.async.wait_group 2;" ::: "memory")

#define MMA_F16(D, A, B0, B1)                                                    \
    asm volatile(                                                                \
        "mma.sync.aligned.m16n8k16.row.col.f32.f16.f16.f32 "                     \
        "{%0,%1,%2,%3}, {%4,%5,%6,%7}, {%8,%9}, {%0,%1,%2,%3};\n"                \
        : "+f"((D)[0]), "+f"((D)[1]), "+f"((D)[2]), "+f"((D)[3])                 \
        : "r"((A)[0]), "r"((A)[1]), "r"((A)[2]), "r"((A)[3]), "r"(B0), "r"(B1))

#define LDSM4(R, addr)                                                           \
    asm volatile("ldmatrix.sync.aligned.m8n8.x4.shared.b16 {%0,%1,%2,%3}, [%4];" \
        : "=r"((R)[0]), "=r"((R)[1]), "=r"((R)[2]), "=r"((R)[3]) : "r"(addr))

// ---------------- init ----------------
__global__ void init_kernel() {
    int tid = threadIdx.x;
    if (tid < NE) { g_psum[tid] = 0.f; g_cnta[tid] = 0; }
    if (tid == 0) g_zsum = 0.f;
}

// ---------------- fp32 -> fp16 conversion pass ----------------
__global__ void cvt_half_kernel(const float* __restrict__ s, int which, int n8) {
    int i = blockIdx.x * blockDim.x + threadIdx.x;
    if (i >= n8) return;
    __half* d = (which == 0) ? g_X_h : (which == 1) ? g_Wg_h : (which == 2) ? g_Wu_h : g_Wo_h;
    float4 v0 = ((const float4*)s)[2 * i];
    float4 v1 = ((const float4*)s)[2 * i + 1];
    __half2 h0 = __floats2half2_rn(v0.x, v0.y);
    __half2 h1 = __floats2half2_rn(v0.z, v0.w);
    __half2 h2 = __floats2half2_rn(v1.x, v1.y);
    __half2 h3 = __floats2half2_rn(v1.z, v1.w);
    uint4 o;
    o.x = *(const uint32_t*)&h0; o.y = *(const uint32_t*)&h1;
    o.z = *(const uint32_t*)&h2; o.w = *(const uint32_t*)&h3;
    ((uint4*)d)[i] = o;
}

// ---------------- router ----------------
__global__ void router_kernel(const float* __restrict__ x, const float* __restrict__ wg) {
    __shared__ float sg[NE * DIM];
    __shared__ float shp[NE];
    __shared__ int   shc[NE];
    __shared__ float shz;
    int tid = threadIdx.x;
    for (int i = tid; i < NE * DIM; i += 256) sg[i] = wg[i];
    if (tid < NE) { shp[tid] = 0.f; shc[tid] = 0; }
    if (tid == 0) shz = 0.f;
    __syncthreads();

    int w = tid >> 5, lane = tid & 31;
    int t = blockIdx.x * 8 + w;
    const float* xt = x + (size_t)t * DIM;
    float acc[NE];
#pragma unroll
    for (int e = 0; e < NE; e++) acc[e] = 0.f;
    for (int j = lane; j < DIM; j += 32) {
        float xv = xt[j];
#pragma unroll
        for (int e = 0; e < NE; e++) acc[e] += xv * sg[e * DIM + j];
    }
#pragma unroll
    for (int o = 16; o > 0; o >>= 1) {
#pragma unroll
        for (int e = 0; e < NE; e++) acc[e] += __shfl_xor_sync(0xffffffffu, acc[e], o);
    }
    if (lane == 0) {
        float m = acc[0];
#pragma unroll
        for (int e = 1; e < NE; e++) m = fmaxf(m, acc[e]);
        float p[NE]; float s = 0.f;
#pragma unroll
        for (int e = 0; e < NE; e++) { p[e] = expf(acc[e] - m); s += p[e]; }
        float inv = 1.f / s;
#pragma unroll
        for (int e = 0; e < NE; e++) p[e] *= inv;
        float lse = m + logf(s);
        int i0 = 0; float b0 = p[0];
#pragma unroll
        for (int e = 1; e < NE; e++) if (p[e] > b0) { b0 = p[e]; i0 = e; }
        int i1 = -1; float b1 = -1.f;
#pragma unroll
        for (int e = 0; e < NE; e++) if (e != i0 && p[e] > b1) { b1 = p[e]; i1 = e; }
        float invs = 1.f / (b0 + b1);
        g_topk[t * 2] = i0; g_topk[t * 2 + 1] = i1;
        g_topp[t * 2] = b0 * invs; g_topp[t * 2 + 1] = b1 * invs;
#pragma unroll
        for (int e = 0; e < NE; e++) atomicAdd(&shp[e], p[e]);
        atomicAdd(&shc[i0], 1);
        atomicAdd(&shc[i1], 1);
        atomicAdd(&shz, lse * lse);
    }
    __syncthreads();
    if (tid < NE) { atomicAdd(&g_psum[tid], shp[tid]); atomicAdd(&g_cnta[tid], shc[tid]); }
    if (tid == 0) atomicAdd(&g_zsum, shz);
}

// ---------------- scan ----------------
__global__ void scan_kernel() {
    int e = blockIdx.x;
    int tid = threadIdx.x;
    int w = tid >> 5, lane = tid & 31;
    unsigned ltm = (1u << lane) - 1u;
    __shared__ int sw0[8], sw1[8], sws[8];
    __shared__ int base0, base1, baseS;
    if (tid == 0) { base0 = 0; base1 = 0; baseS = 0; }
    __syncthreads();
    for (int b = 0; b < T_TOK; b += 256) {
        int t = b + tid;
        int i0 = g_topk[t * 2], i1 = g_topk[t * 2 + 1];
        int a0 = (i0 == e) ? 1 : 0;
        int a1 = (i1 == e) ? 1 : 0;
        unsigned m0b = __ballot_sync(0xffffffffu, a0);
        unsigned m1b = __ballot_sync(0xffffffffu, a1);
        if (lane == 0) { sw0[w] = __popc(m0b); sw1[w] = __popc(m1b); }
        __syncthreads();
        int off0 = base0, off1 = base1;
        for (int j = 0; j < w; j++) { off0 += sw0[j]; off1 += sw1[j]; }
        int r0 = off0 + __popc(m0b & ltm);
        int r1 = off1 + __popc(m1b & ltm);
        int k0 = a0 && (r0 < CAP);
        int k1 = a1 && (r1 < CAP);
        int sel = (k0 || k1) ? 1 : 0;
        unsigned msb = __ballot_sync(0xffffffffu, sel);
        if (lane == 0) sws[w] = __popc(msb);
        __syncthreads();
        int offS = baseS;
        for (int j = 0; j < w; j++) offS += sws[j];
        int pos = offS + __popc(msb & ltm);
        if (sel) g_tok[e * MAXR + pos] = t;
        if (a0) { g_wk[t * 2]     = k0 ? g_topp[t * 2]     : 0.f; g_rowidx[t * 2]     = k0 ? (e * MAXR + pos) : 0; }
        if (a1) { g_wk[t * 2 + 1] = k1 ? g_topp[t * 2 + 1] : 0.f; g_rowidx[t * 2 + 1] = k1 ? (e * MAXR + pos) : 0; }
        __syncthreads();
        if (tid == 0) {
            int t0 = 0, t1 = 0, ts = 0;
            for (int j = 0; j < 8; j++) { t0 += sw0[j]; t1 += sw1[j]; ts += sws[j]; }
            base0 += t0; base1 += t1; baseS += ts;
        }
        __syncthreads();
    }
    if (tid == 0) g_cnt[e] = baseS;
}

// ---------------- GEMM config ----------------
#define BM 128
#define BK 32                  // halves per k-tile (2 x k16 mma steps)
#define LDH 40                 // halves per smem row (32 data + 8 pad), LDSM-conflict-free
#define G1_STAGE 20480u        // bytes: A(128x40x2=10240) + G(64x40x2=5120) + U(5120)
#define G1_GOFF  10240u
#define G1_UOFF  15360u
#define G2_STAGE 20480u        // bytes: A(10240) + B(128x40x2=10240)
#define G2_BOFF  10240u
#define NSTAGE 4

// GEMM1: H = silu(Xg @ Wg^T) * (Xg @ Wu^T); BM=128, BN=64 (per matrix)
// warps 4(m) x 2(n), warp tile 32x32, LDSM fragments, 2 CTAs/SM
__global__ __launch_bounds__(256, 2) void gemm1_kernel() {
    int e = blockIdx.z;
    int cnt = g_cnt[e];
    int m0 = blockIdx.y * BM;
    if (m0 >= cnt) return;
    int n0 = blockIdx.x * 64;

    extern __shared__ __half sm[];
    __shared__ int stok[BM];
    int tid = threadIdx.x;
    if (tid < BM) { int r = m0 + tid; stok[tid] = (r < cnt) ? g_tok[e * MAXR + r] : 0; }
    __syncthreads();

    uint32_t sb = su32(sm);
    int rr = tid >> 1;
    int ko = (tid & 1) * 16;
    const __half* srcA = g_X_h + (size_t)stok[rr] * DIM + ko;
    uint32_t dstA = sb + (uint32_t)(rr * LDH + ko) * 2;
    int bro = (tid & 127) >> 1;   // 0..63
    const __half* srcB = ((tid < 128) ? g_Wg_h : g_Wu_h) + ((size_t)e * FF + n0 + bro) * DIM + ko;
    uint32_t dstB = sb + ((tid < 128) ? G1_GOFF : G1_UOFF) + (uint32_t)(bro * LDH + ko) * 2;

#define G1_ISSUE(s, kt) do {                                           \
        uint32_t b_ = (uint32_t)(s) * G1_STAGE;                        \
        int kh_ = (kt) * BK;                                           \
        cp16(dstA + b_, srcA + kh_); cp16(dstA + b_ + 16, srcA + kh_ + 8); \
        cp16(dstB + b_, srcB + kh_); cp16(dstB + b_ + 16, srcB + kh_ + 8); \
    } while (0)

    int lane = tid & 31, wid = tid >> 5;
    int g = lane >> 2, t4 = lane & 3;
    int wm = wid & 3, wn = wid >> 2;   // 4 x 2 warp grid

    uint32_t offA[2], offB[2];
#pragma unroll
    for (int im = 0; im < 2; im++)
        offA[im] = (uint32_t)((wm * 32 + im * 16 + (lane & 15)) * LDH + (lane >> 4) * 8) * 2;
#pragma unroll
    for (int p = 0; p < 2; p++)
        offB[p] = G1_GOFF + (uint32_t)((wn * 32 + (p * 2 + (lane >> 4)) * 8 + (lane & 7)) * LDH
                                       + ((lane >> 3) & 1) * 8) * 2;

    float ag[2][4][4], au[2][4][4];
#pragma unroll
    for (int i = 0; i < 2; i++)
#pragma unroll
        for (int j = 0; j < 4; j++)
#pragma unroll
            for (int c = 0; c < 4; c++) { ag[i][j][c] = 0.f; au[i][j][c] = 0.f; }

    G1_ISSUE(0, 0); CP_COMMIT();
    G1_ISSUE(1, 1); CP_COMMIT();
    G1_ISSUE(2, 2); CP_COMMIT();

    const int NK = DIM / BK;  // 24
    for (int kt = 0; kt < NK; kt++) {
        CP_WAIT_2();
        __syncthreads();
        if (kt + 3 < NK) G1_ISSUE((kt + 3) % NSTAGE, kt + 3);
        CP_COMMIT();
        uint32_t stb = sb + (uint32_t)(kt % NSTAGE) * G1_STAGE;
#pragma unroll
        for (int km = 0; km < 2; km++) {
            uint32_t kmo = km * 32;
            uint32_t a[2][4], gq[2][4], uq[2][4];
            LDSM4(a[0], stb + offA[0] + kmo);
            LDSM4(a[1], stb + offA[1] + kmo);
            LDSM4(gq[0], stb + offB[0] + kmo);
            LDSM4(gq[1], stb + offB[1] + kmo);
            LDSM4(uq[0], stb + offB[0] + (G1_UOFF - G1_GOFF) + kmo);
            LDSM4(uq[1], stb + offB[1] + (G1_UOFF - G1_GOFF) + kmo);
#pragma unroll
            for (int p = 0; p < 2; p++) {
#pragma unroll
                for (int s = 0; s < 2; s++) {
                    int jn = p * 2 + s;
#pragma unroll
                    for (int im = 0; im < 2; im++) {
                        MMA_F16(ag[im][jn], a[im], gq[p][s * 2], gq[p][s * 2 + 1]);
                        MMA_F16(au[im][jn], a[im], uq[p][s * 2], uq[p][s * 2 + 1]);
                    }
                }
            }
        }
    }

    // epilogue: h = silu(g) * u, store fp16 H
#pragma unroll
    for (int im = 0; im < 2; im++) {
#pragma unroll
        for (int jn = 0; jn < 4; jn++) {
            int rl  = wm * 32 + im * 16 + g;
            int col = n0 + wn * 32 + jn * 8 + t4 * 2;
            size_t b0i = (size_t)(e * MAXR + m0 + rl) * FF + col;
            size_t b1i = (size_t)(e * MAXR + m0 + rl + 8) * FF + col;
            float gg, uu, h0x, h0y, h1x, h1y;
            gg = ag[im][jn][0]; uu = au[im][jn][0]; h0x = gg / (1.f + expf(-gg)) * uu;
            gg = ag[im][jn][1]; uu = au[im][jn][1]; h0y = gg / (1.f + expf(-gg)) * uu;
            gg = ag[im][jn][2]; uu = au[im][jn][2]; h1x = gg / (1.f + expf(-gg)) * uu;
            gg = ag[im][jn][3]; uu = au[im][jn][3]; h1y = gg / (1.f + expf(-gg)) * uu;
            *(__half2*)&g_H_h[b0i] = __floats2half2_rn(h0x, h0y);
            *(__half2*)&g_H_h[b1i] = __floats2half2_rn(h1x, h1y);
        }
    }
}

// GEMM2: Y = H @ Wo^T; BM=128, BN=128, warps 4(m)x2(n), warp tile 32x64, 2 CTAs/SM
__global__ __launch_bounds__(256, 2) void gemm2_kernel() {
    int e = blockIdx.z;
    int cnt = g_cnt[e];
    int m0 = blockIdx.y * BM;
    if (m0 >= cnt) return;
    int n0 = blockIdx.x * 128;

    extern __shared__ __half sm[];
    int tid = threadIdx.x;
    uint32_t sb = su32(sm);
    int rr = tid >> 1;
    int ko = (tid & 1) * 16;
    const __half* srcA = g_H_h + (size_t)(e * MAXR + m0 + rr) * FF + ko;
    uint32_t dstA = sb + (uint32_t)(rr * LDH + ko) * 2;
    const __half* srcB = g_Wo_h + ((size_t)e * DIM + n0 + rr) * FF + ko;
    uint32_t dstB = sb + G2_BOFF + (uint32_t)(rr * LDH + ko) * 2;

#define G2_ISSUE(s, kt) do {                                           \
        uint32_t b_ = (uint32_t)(s) * G2_STAGE;                        \
        int kh_ = (kt) * BK;                                           \
        cp16(dstA + b_, srcA + kh_); cp16(dstA + b_ + 16, srcA + kh_ + 8); \
        cp16(dstB + b_, srcB + kh_); cp16(dstB + b_ + 16, srcB + kh_ + 8); \
    } while (0)

    int lane = tid & 31, wid = tid >> 5;
    int g = lane >> 2, t4 = lane & 3;
    int wm = wid & 3, wn = wid >> 2;

    uint32_t offA[2], offB[4];
#pragma unroll
    for (int im = 0; im < 2; im++)
        offA[im] = (uint32_t)((wm * 32 + im * 16 + (lane & 15)) * LDH + (lane >> 4) * 8) * 2;
#pragma unroll
    for (int p = 0; p < 4; p++)
        offB[p] = G2_BOFF + (uint32_t)((wn * 64 + (p * 2 + (lane >> 4)) * 8 + (lane & 7)) * LDH
                                       + ((lane >> 3) & 1) * 8) * 2;

    float acc[2][8][4];
#pragma unroll
    for (int i = 0; i < 2; i++)
#pragma unroll
        for (int j = 0; j < 8; j++)
#pragma unroll
            for (int c = 0; c < 4; c++) acc[i][j][c] = 0.f;

    G2_ISSUE(0, 0); CP_COMMIT();
    G2_ISSUE(1, 1); CP_COMMIT();
    G2_ISSUE(2, 2); CP_COMMIT();

    const int NK = FF / BK;  // 96
    for (int kt = 0; kt < NK; kt++) {
        CP_WAIT_2();
        __syncthreads();
        if (kt + 3 < NK) G2_ISSUE((kt + 3) % NSTAGE, kt + 3);
        CP_COMMIT();
        uint32_t stb = sb + (uint32_t)(kt % NSTAGE) * G2_STAGE;
#pragma unroll
        for (int km = 0; km < 2; km++) {
            uint32_t kmo = km * 32;
            uint32_t a[2][4], bq[4][4];
            LDSM4(a[0], stb + offA[0] + kmo);
            LDSM4(a[1], stb + offA[1] + kmo);
#pragma unroll
            for (int p = 0; p < 4; p++) LDSM4(bq[p], stb + offB[p] + kmo);
#pragma unroll
            for (int p = 0; p < 4; p++) {
#pragma unroll
                for (int s = 0; s < 2; s++) {
                    int jn = p * 2 + s;
#pragma unroll
                    for (int im = 0; im < 2; im++)
                        MMA_F16(acc[im][jn], a[im], bq[p][s * 2], bq[p][s * 2 + 1]);
                }
            }
        }
    }

#pragma unroll
    for (int im = 0; im < 2; im++) {
#pragma unroll
        for (int jn = 0; jn < 8; jn++) {
            int rl  = wm * 32 + im * 16 + g;
            int col = n0 + wn * 64 + jn * 8 + t4 * 2;
            size_t b0i = (size_t)(e * MAXR + m0 + rl) * DIM + col;
            size_t b1i = (size_t)(e * MAXR + m0 + rl + 8) * DIM + col;
            *(float2*)&g_Y[b0i] = make_float2(acc[im][jn][0], acc[im][jn][1]);
            *(float2*)&g_Y[b1i] = make_float2(acc[im][jn][2], acc[im][jn][3]);
        }
    }
}

// ---------------- combine ----------------
__global__ void combine_kernel(float* __restrict__ out) {
    int gi = blockIdx.x * 256 + threadIdx.x;
    int t = gi / (DIM / 4);
    int c = (gi % (DIM / 4)) * 4;
    float w0 = g_wk[t * 2], w1 = g_wk[t * 2 + 1];
    float4 acc = make_float4(0.f, 0.f, 0.f, 0.f);
    if (w0 > 0.f) {
        const float4 y = *(const float4*)&g_Y[(size_t)g_rowidx[t * 2] * DIM + c];
        acc.x = w0 * y.x; acc.y = w0 * y.y; acc.z = w0 * y.z; acc.w = w0 * y.w;
    }
    if (w1 > 0.f) {
        const float4 y = *(const float4*)&g_Y[(size_t)g_rowidx[t * 2 + 1] * DIM + c];
        acc.x += w1 * y.x; acc.y += w1 * y.y; acc.z += w1 * y.z; acc.w += w1 * y.w;
    }
    *(float4*)(out + (size_t)gi * 4) = acc;
}

// ---------------- finalize ----------------
__global__ void finalize_kernel(float* __restrict__ out, int out_size) {
    if (threadIdx.x == 0 && out_size > T_TOK * DIM) {
        float lb = 0.f;
        for (int e = 0; e < NE; e++) {
            float f = (float)g_cnta[e] / (float)(T_TOK * 2);
            float P = g_psum[e] / (float)T_TOK;
            lb += f * P;
        }
        lb *= (float)NE;
        float z = g_zsum / (float)T_TOK;
        out[T_TOK * DIM] = 0.01f * lb + 0.001f * z;
    }
}

// ---------------- launch ----------------
extern "C" void kernel_launch(void* const* d_in, const int* in_sizes, int n_in,
                              void* d_out, int out_size) {
    (void)in_sizes; (void)n_in;
    const float* x   = (const float*)d_in[0];
    const float* wg  = (const float*)d_in[1];
    const float* wig = (const float*)d_in[2];
    const float* wiu = (const float*)d_in[3];
    const float* wo  = (const float*)d_in[4];
    float* out = (float*)d_out;

    const int G1_SMEM = NSTAGE * G1_STAGE;  // 81920 bytes
    const int G2_SMEM = NSTAGE * G2_STAGE;  // 81920 bytes
    cudaFuncSetAttribute(gemm1_kernel, cudaFuncAttributeMaxDynamicSharedMemorySize, G1_SMEM);
    cudaFuncSetAttribute(gemm2_kernel, cudaFuncAttributeMaxDynamicSharedMemorySize, G2_SMEM);

    const int NW8 = (NE * FF * DIM) / 8;   // 2359296
    const int NX8 = (T_TOK * DIM) / 8;     // 786432

    init_kernel<<<1, 32>>>();
    cvt_half_kernel<<<(NX8 + 255) / 256, 256>>>(x, 0, NX8);
    cvt_half_kernel<<<(NW8 + 255) / 256, 256>>>(wig, 1, NW8);
    cvt_half_kernel<<<(NW8 + 255) / 256, 256>>>(wiu, 2, NW8);
    cvt_half_kernel<<<(NW8 + 255) / 256, 256>>>(wo, 3, NW8);
    router_kernel<<<T_TOK / 8, 256>>>(x, wg);
    scan_kernel<<<NE, 256>>>();
    gemm1_kernel<<<dim3(FF / 64, MAXR / BM, NE), 256, G1_SMEM>>>();
    gemm2_kernel<<<dim3(DIM / 128, MAXR / BM, NE), 256, G2_SMEM>>>();
    combine_kernel<<<(T_TOK * DIM / 4) / 256, 256>>>(out);
    finalize_kernel<<<1, 1>>>(out, out_size);
}